// round 14
// baseline (speedup 1.0000x reference)
#include <cuda_runtime.h>
#include <cuda_bf16.h>
#include <cstdint>

// Depth-to-space, SCALE=2 — session-best config; final probe: write-through
// stores (__stwt) instead of streaming-allocate (__stcs).
// in : [B=16, H=128, W=128, C=256] fp32
// out: [B, 2H=256, 2W=256, C/4=64] fp32
// out[b, 2h+j, 2w+k, c] = in[b, h, w, 4c + 2k + j]
//
// Session evidence (all alternatives benched):
//  - 256-thread CTAs, __launch_bounds__(256,8): best point. 1024-thr CTAs,
//    persistent grid regressed; MLP=8 neutral vs 4; store reorder neutral.
//  - 4 front-batched LDG.128.cs (64B contiguous/thread) -> register 4x4
//    transpose -> 4 STG.128 stores. Every access 128B-sector-coalesced per
//    warp; all output lines fully written (no read-for-ownership).
//  - Best measured: 74.2us kernel, 6.50 TB/s HBM (81% of spec), all compute
//    pipes idle. This round tests STG.WT: write stream skips L2 allocation,
//    the last unmeasured cache-policy bit. Expected neutral (LTS cap is
//    path-independent per B300_MICROARCH); revert to __stcs if regression.

__global__ void __launch_bounds__(256, 8)
d2s_kernel(const float4* __restrict__ in4, float4* __restrict__ out4)
{
    // 16*128*128 pixels * 16 groups = 4,194,304 threads
    unsigned idx = blockIdx.x * 256u + threadIdx.x;

    unsigned g     = idx & 15u;          // out channel group: 4g..4g+3
    unsigned pixel = idx >> 4;           // b*H*W + h*W + w
    unsigned w     = pixel & 127u;
    unsigned h     = (pixel >> 7) & 127u;
    unsigned b     = pixel >> 14;

    // Front-batched streaming loads: 64B contiguous per thread (MLP_p1 = 4)
    unsigned base4 = idx << 2;
    float4 v0 = __ldcs(in4 + base4 + 0);
    float4 v1 = __ldcs(in4 + base4 + 1);
    float4 v2 = __ldcs(in4 + base4 + 2);
    float4 v3 = __ldcs(in4 + base4 + 3);

    // Output offsets in float4 units:
    // o(j,k) = ((r0+j)*256 + 2w+k)*16 + g = ((r0+j)<<12) + ((2w+k)<<4) + g
    unsigned r0  = (b << 8) + (h << 1);            // output row for j=0
    unsigned o00 = (r0 << 12) + (w << 5) + g;
    unsigned o10 = o00 + (1u << 12);               // +1 output row (j=1)
    unsigned o01 = o00 + 16u;                      // +1 output col (k=1)
    unsigned o11 = o10 + 16u;

    // s_jk = component (2k+j) of {v0..v3}; component (2k+j) of float4 m is
    // input channel 16g+4m+2k+j = output channel 4g+m at position (j,k).
    __stwt(out4 + o00, make_float4(v0.x, v1.x, v2.x, v3.x));  // j=0,k=0
    __stwt(out4 + o10, make_float4(v0.y, v1.y, v2.y, v3.y));  // j=1,k=0
    __stwt(out4 + o01, make_float4(v0.z, v1.z, v2.z, v3.z));  // j=0,k=1
    __stwt(out4 + o11, make_float4(v0.w, v1.w, v2.w, v3.w));  // j=1,k=1
}

extern "C" void kernel_launch(void* const* d_in, const int* in_sizes, int n_in,
                              void* d_out, int out_size)
{
    const float4* in4 = (const float4*)d_in[0];
    float4* out4 = (float4*)d_out;

    // total threads = in_sizes[0] / 16 = 4,194,304
    unsigned n_threads = (unsigned)(in_sizes[0] / 16);
    unsigned n_blocks  = (n_threads + 255u) / 256u;   // 16384

    d2s_kernel<<<n_blocks, 256>>>(in4, out4);
}

// round 15
// speedup vs baseline: 1.3072x; 1.3072x over previous
#include <cuda_runtime.h>
#include <cuda_bf16.h>
#include <cstdint>

// Depth-to-space, SCALE=2 — FINAL kernel (session-best, fully converged).
// in : [B=16, H=128, W=128, C=256] fp32
// out: [B, 2H=256, 2W=256, C/4=64] fp32
// out[b, 2h+j, 2w+k, c] = in[b, h, w, 4c + 2k + j]
//
// Full lever matrix measured this session:
//  - block {256 best, 1024 worse}; occupancy {8 CTAs/SM best};
//    persistent grid regressed; MLP {4 sufficient, 8 neutral, 1 worse};
//    store order {original best}; store policy {.cs best, .wt -25% --
//    write-through breaks L2 full-line write-combining of the store stream}.
//  - Config: 4 front-batched LDG.128.cs (64B contiguous/thread) ->
//    register 4x4 transpose -> 4 STG.128.cs. Every access is fully
//    128B-sector-coalesced per warp; all output lines written in full
//    (no read-for-ownership traffic).
//  - Reproduced best: 74.2us kernel, 6.50 TB/s HBM (81% of 8TB/s spec),
//    DRAM busy 82%, all compute pipes idle -> mixed r+w HBM roofline.

__global__ void __launch_bounds__(256, 8)
d2s_kernel(const float4* __restrict__ in4, float4* __restrict__ out4)
{
    // 16*128*128 pixels * 16 groups = 4,194,304 threads
    unsigned idx = blockIdx.x * 256u + threadIdx.x;

    unsigned g     = idx & 15u;          // out channel group: 4g..4g+3
    unsigned pixel = idx >> 4;           // b*H*W + h*W + w
    unsigned w     = pixel & 127u;
    unsigned h     = (pixel >> 7) & 127u;
    unsigned b     = pixel >> 14;

    // Front-batched streaming loads: 64B contiguous per thread (MLP_p1 = 4)
    unsigned base4 = idx << 2;
    float4 v0 = __ldcs(in4 + base4 + 0);
    float4 v1 = __ldcs(in4 + base4 + 1);
    float4 v2 = __ldcs(in4 + base4 + 2);
    float4 v3 = __ldcs(in4 + base4 + 3);

    // Output offsets in float4 units:
    // o(j,k) = ((r0+j)*256 + 2w+k)*16 + g = ((r0+j)<<12) + ((2w+k)<<4) + g
    unsigned r0  = (b << 8) + (h << 1);            // output row for j=0
    unsigned o00 = (r0 << 12) + (w << 5) + g;
    unsigned o10 = o00 + (1u << 12);               // +1 output row (j=1)
    unsigned o01 = o00 + 16u;                      // +1 output col (k=1)
    unsigned o11 = o10 + 16u;

    // s_jk = component (2k+j) of {v0..v3}; component (2k+j) of float4 m is
    // input channel 16g+4m+2k+j = output channel 4g+m at position (j,k).
    __stcs(out4 + o00, make_float4(v0.x, v1.x, v2.x, v3.x));  // j=0,k=0
    __stcs(out4 + o10, make_float4(v0.y, v1.y, v2.y, v3.y));  // j=1,k=0
    __stcs(out4 + o01, make_float4(v0.z, v1.z, v2.z, v3.z));  // j=0,k=1
    __stcs(out4 + o11, make_float4(v0.w, v1.w, v2.w, v3.w));  // j=1,k=1
}

extern "C" void kernel_launch(void* const* d_in, const int* in_sizes, int n_in,
                              void* d_out, int out_size)
{
    const float4* in4 = (const float4*)d_in[0];
    float4* out4 = (float4*)d_out;

    // total threads = in_sizes[0] / 16 = 4,194,304
    unsigned n_threads = (unsigned)(in_sizes[0] / 16);
    unsigned n_blocks  = (n_threads + 255u) / 256u;   // 16384

    d2s_kernel<<<n_blocks, 256>>>(in4, out4);
}